// round 1
// baseline (speedup 1.0000x reference)
#include <cuda_runtime.h>
#include <math.h>

#define S_LEN 2048
#define HID   2560
#define NH    32
#define NKV   8
#define HD    128
#define QDIM  (NH*HD)    // 4096
#define KVDIM (NKV*HD)   // 1024

// Scratch (static device arrays; no allocation allowed)
__device__ float g_Q [S_LEN*QDIM];
__device__ float g_K [S_LEN*KVDIM];
__device__ float g_V [S_LEN*KVDIM];
__device__ float g_AO[S_LEN*QDIM];

// ---------------------------------------------------------------------------
// SGEMM NT: C[M,N] = A[M,K] * B[N,K]^T   (A,B row-major, K contiguous)
// BM=BN=128, BK=16, 256 threads, 8x8 micro-tile per thread.
// ---------------------------------------------------------------------------
__global__ void __launch_bounds__(256) sgemm_nt(const float* __restrict__ A,
                                                const float* __restrict__ B,
                                                float* __restrict__ C,
                                                int M, int N, int Kd) {
    __shared__ float As[16][128];
    __shared__ float Bs[16][128];

    const int tid = threadIdx.x;
    const int tx = tid & 15;        // 0..15 -> N
    const int ty = tid >> 4;        // 0..15 -> M
    const int row0 = blockIdx.y * 128 + ty * 8;
    const int col0 = blockIdx.x * 128 + tx * 8;

    const int lr = tid >> 2;         // 0..63
    const int lk = (tid & 3) * 4;    // 0,4,8,12

    const float* Ap = A + (size_t)(blockIdx.y * 128) * Kd;
    const float* Bp = B + (size_t)(blockIdx.x * 128) * Kd;

    float acc[8][8];
#pragma unroll
    for (int i = 0; i < 8; i++)
#pragma unroll
        for (int j = 0; j < 8; j++) acc[i][j] = 0.f;

    for (int k0 = 0; k0 < Kd; k0 += 16) {
#pragma unroll
        for (int i = 0; i < 2; i++) {
            int r = lr + i * 64;
            float4 a = *(const float4*)(Ap + (size_t)r * Kd + k0 + lk);
            As[lk + 0][r] = a.x; As[lk + 1][r] = a.y;
            As[lk + 2][r] = a.z; As[lk + 3][r] = a.w;
            float4 b = *(const float4*)(Bp + (size_t)r * Kd + k0 + lk);
            Bs[lk + 0][r] = b.x; Bs[lk + 1][r] = b.y;
            Bs[lk + 2][r] = b.z; Bs[lk + 3][r] = b.w;
        }
        __syncthreads();

#pragma unroll
        for (int kk = 0; kk < 16; kk++) {
            float4 a0 = *(float4*)&As[kk][ty * 8];
            float4 a1 = *(float4*)&As[kk][ty * 8 + 4];
            float4 b0 = *(float4*)&Bs[kk][tx * 8];
            float4 b1 = *(float4*)&Bs[kk][tx * 8 + 4];
            float a[8] = {a0.x, a0.y, a0.z, a0.w, a1.x, a1.y, a1.z, a1.w};
            float b[8] = {b0.x, b0.y, b0.z, b0.w, b1.x, b1.y, b1.z, b1.w};
#pragma unroll
            for (int i = 0; i < 8; i++)
#pragma unroll
                for (int j = 0; j < 8; j++)
                    acc[i][j] = fmaf(a[i], b[j], acc[i][j]);
        }
        __syncthreads();
    }

#pragma unroll
    for (int i = 0; i < 8; i++) {
        float4 c0 = {acc[i][0], acc[i][1], acc[i][2], acc[i][3]};
        float4 c1 = {acc[i][4], acc[i][5], acc[i][6], acc[i][7]};
        *(float4*)(C + (size_t)(row0 + i) * N + col0)     = c0;
        *(float4*)(C + (size_t)(row0 + i) * N + col0 + 4) = c1;
    }
}

// ---------------------------------------------------------------------------
// Fused per-head RMSNorm + RoPE, in-place on X[S, nheads*128].
// One warp per (s, head) row. rotate_half via shfl_xor(16).
// ---------------------------------------------------------------------------
__global__ void rms_rope_kernel(float* __restrict__ X, const float* __restrict__ w,
                                const float* __restrict__ cosp, const float* __restrict__ sinp,
                                int nheads, int nrows) {
    int warp = (blockIdx.x * blockDim.x + threadIdx.x) >> 5;
    int lane = threadIdx.x & 31;
    if (warp >= nrows) return;
    int s = warp / nheads;

    float* p = X + (size_t)warp * HD;
    float4 x = *(float4*)(p + lane * 4);

    float ss = x.x * x.x + x.y * x.y + x.z * x.z + x.w * x.w;
#pragma unroll
    for (int o = 16; o; o >>= 1) ss += __shfl_xor_sync(0xffffffffu, ss, o);
    float r = rsqrtf(ss * (1.0f / HD) + 1e-6f);

    float4 wv = *(const float4*)(w + lane * 4);
    x.x *= r * wv.x; x.y *= r * wv.y; x.z *= r * wv.z; x.w *= r * wv.w;

    float4 rot;
    rot.x = __shfl_xor_sync(0xffffffffu, x.x, 16);
    rot.y = __shfl_xor_sync(0xffffffffu, x.y, 16);
    rot.z = __shfl_xor_sync(0xffffffffu, x.z, 16);
    rot.w = __shfl_xor_sync(0xffffffffu, x.w, 16);
    float sgn = (lane < 16) ? -1.f : 1.f;

    float4 cv = *(const float4*)(cosp + (size_t)s * HD + lane * 4);
    float4 sv = *(const float4*)(sinp + (size_t)s * HD + lane * 4);

    float4 o;
    o.x = x.x * cv.x + sgn * rot.x * sv.x;
    o.y = x.y * cv.y + sgn * rot.y * sv.y;
    o.z = x.z * cv.z + sgn * rot.z * sv.z;
    o.w = x.w * cv.w + sgn * rot.w * sv.w;
    *(float4*)(p + lane * 4) = o;
}

// ---------------------------------------------------------------------------
// Causal GQA flash attention (online softmax).
// Block: 512 threads = 16 warps, 16 query rows of one head.
// K/V tiles of 64 rows staged in dynamic smem (64KB).
// ---------------------------------------------------------------------------
__global__ void __launch_bounds__(512) flash_kernel(const float* __restrict__ Q,
                                                    const float* __restrict__ K,
                                                    const float* __restrict__ V,
                                                    float* __restrict__ O) {
    extern __shared__ float sm[];
    float* Ks = sm;              // [64][128]
    float* Vs = sm + 64 * 128;   // [64][128]

    const int tid  = threadIdx.x;
    const int w    = tid >> 5;
    const int lane = tid & 31;
    const int h    = blockIdx.y;
    const int kvh  = h >> 2;
    const int s    = blockIdx.x * 16 + w;
    const float scale = 0.08838834764831845f;  // 1/sqrt(128)

    float4 qv = *(const float4*)(Q + (size_t)s * QDIM + h * HD + lane * 4);
    float4 acc = {0.f, 0.f, 0.f, 0.f};
    float m = -1e30f, l = 0.f;

    const int smax = blockIdx.x * 16 + 15;
    for (int kb = 0; kb <= smax; kb += 64) {
#pragma unroll
        for (int i = 0; i < 4; i++) {
            int f = tid + i * 512;
            int r = f >> 5, c4 = (f & 31) * 4;
            *(float4*)(Ks + r * 128 + c4) =
                *(const float4*)(K + (size_t)(kb + r) * KVDIM + kvh * HD + c4);
            *(float4*)(Vs + r * 128 + c4) =
                *(const float4*)(V + (size_t)(kb + r) * KVDIM + kvh * HD + c4);
        }
        __syncthreads();

        int jmax = s - kb + 1;
        if (jmax > 64) jmax = 64;
        for (int j = 0; j < jmax; j++) {
            float4 kv = *(const float4*)(Ks + j * 128 + lane * 4);
            float d = qv.x * kv.x + qv.y * kv.y + qv.z * kv.z + qv.w * kv.w;
#pragma unroll
            for (int o = 16; o; o >>= 1) d += __shfl_xor_sync(0xffffffffu, d, o);
            float sc = d * scale;
            float mn = fmaxf(m, sc);
            float corr = __expf(m - mn);
            float p = __expf(sc - mn);
            l = l * corr + p;
            float4 vv = *(const float4*)(Vs + j * 128 + lane * 4);
            acc.x = acc.x * corr + p * vv.x;
            acc.y = acc.y * corr + p * vv.y;
            acc.z = acc.z * corr + p * vv.z;
            acc.w = acc.w * corr + p * vv.w;
            m = mn;
        }
        __syncthreads();
    }

    float inv = 1.f / l;
    float4 o = {acc.x * inv, acc.y * inv, acc.z * inv, acc.w * inv};
    *(float4*)(O + (size_t)s * QDIM + h * HD + lane * 4) = o;
}

// ---------------------------------------------------------------------------
extern "C" void kernel_launch(void* const* d_in, const int* in_sizes, int n_in,
                              void* d_out, int out_size) {
    const float* X    = (const float*)d_in[0];
    const float* cosp = (const float*)d_in[1];
    const float* sinp = (const float*)d_in[2];
    const float* Wq   = (const float*)d_in[3];
    const float* Wk   = (const float*)d_in[4];
    const float* Wv   = (const float*)d_in[5];
    const float* Wo   = (const float*)d_in[6];
    const float* qw   = (const float*)d_in[7];
    const float* kw   = (const float*)d_in[8];
    float* out = (float*)d_out;

    float *Q, *K, *V, *AO;
    cudaGetSymbolAddress((void**)&Q,  g_Q);
    cudaGetSymbolAddress((void**)&K,  g_K);
    cudaGetSymbolAddress((void**)&V,  g_V);
    cudaGetSymbolAddress((void**)&AO, g_AO);

    // Projections: C = X @ W^T
    sgemm_nt<<<dim3(QDIM / 128,  S_LEN / 128), 256>>>(X, Wq, Q, S_LEN, QDIM,  HID);
    sgemm_nt<<<dim3(KVDIM / 128, S_LEN / 128), 256>>>(X, Wk, K, S_LEN, KVDIM, HID);
    sgemm_nt<<<dim3(KVDIM / 128, S_LEN / 128), 256>>>(X, Wv, V, S_LEN, KVDIM, HID);

    // RMSNorm + RoPE (in place)
    rms_rope_kernel<<<(S_LEN * NH)  / 8, 256>>>(Q, qw, cosp, sinp, NH,  S_LEN * NH);
    rms_rope_kernel<<<(S_LEN * NKV) / 8, 256>>>(K, kw, cosp, sinp, NKV, S_LEN * NKV);

    // Flash attention
    int smem = 2 * 64 * 128 * sizeof(float);  // 64KB
    cudaFuncSetAttribute(flash_kernel, cudaFuncAttributeMaxDynamicSharedMemorySize, smem);
    flash_kernel<<<dim3(S_LEN / 16, NH), 512, smem>>>(Q, K, V, AO);

    // Output projection: out = AO @ Wo^T
    sgemm_nt<<<dim3(HID / 128, S_LEN / 128), 256>>>(AO, Wo, out, S_LEN, HID, QDIM);
}

// round 3
// speedup vs baseline: 1.4446x; 1.4446x over previous
#include <cuda_runtime.h>
#include <math.h>
#include <stdint.h>

#define S_LEN 2048
#define HID   2560
#define NH    32
#define NKV   8
#define HD    128
#define QDIM  (NH*HD)    // 4096
#define KVDIM (NKV*HD)   // 1024

// Scratch (static device arrays; no allocation allowed)
__device__ float g_Q [S_LEN*QDIM];
__device__ float g_K [S_LEN*KVDIM];
__device__ float g_V [S_LEN*KVDIM];
__device__ float g_AO[S_LEN*QDIM];

// ---------------------------------------------------------------------------
// TF32 tensor-core GEMM NT: C[M,N] = A[M,K] * B[N,K]^T
// BM=BN=128, BK=16, 256 threads (8 warps, 2x4), warp tile 64x32.
// mma.sync.m16n8k8 tf32, fp32 accumulate. cvt.rna on the smem-store path.
// Smem row stride = 20 floats -> conflict-free fragment loads.
// ---------------------------------------------------------------------------
__device__ __forceinline__ uint32_t f2tf(float x) {
    uint32_t y;
    asm("cvt.rna.tf32.f32 %0, %1;" : "=r"(y) : "f"(x));
    return y;
}

__device__ __forceinline__ void mma_tf32(float* d, const uint32_t* a, const uint32_t* b) {
    asm volatile(
        "mma.sync.aligned.m16n8k8.row.col.f32.tf32.tf32.f32 "
        "{%0,%1,%2,%3}, {%4,%5,%6,%7}, {%8,%9}, {%0,%1,%2,%3};\n"
        : "+f"(d[0]), "+f"(d[1]), "+f"(d[2]), "+f"(d[3])
        : "r"(a[0]), "r"(a[1]), "r"(a[2]), "r"(a[3]), "r"(b[0]), "r"(b[1]));
}

#define SMS 20  // smem row stride in words

__global__ void __launch_bounds__(256, 2) tf32_gemm_nt(const float* __restrict__ A,
                                                       const float* __restrict__ B,
                                                       float* __restrict__ C,
                                                       int M, int N, int Kd) {
    __shared__ uint32_t As[128 * SMS];
    __shared__ uint32_t Bs[128 * SMS];

    const int tid  = threadIdx.x;
    const int wid  = tid >> 5;
    const int lane = tid & 31;
    const int wm   = (wid & 1) * 64;   // warp row base in tile
    const int wn   = (wid >> 1) * 32;  // warp col base in tile
    const int g    = lane >> 2;        // group id 0..7
    const int c    = lane & 3;         // thread-in-group 0..3

    // global staging: each thread loads 2 float4 from A and 2 from B per tile
    const int sr = tid >> 2;           // 0..63
    const int sc = (tid & 3) * 4;      // 0,4,8,12
    const float* Ap = A + (size_t)(blockIdx.y * 128 + sr) * Kd + sc;
    const float* Bp = B + (size_t)(blockIdx.x * 128 + sr) * Kd + sc;

    float acc[4][4][4];
#pragma unroll
    for (int i = 0; i < 4; i++)
#pragma unroll
        for (int j = 0; j < 4; j++)
#pragma unroll
            for (int k = 0; k < 4; k++) acc[i][j][k] = 0.f;

    float4 ra0 = *(const float4*)(Ap);
    float4 ra1 = *(const float4*)(Ap + (size_t)64 * Kd);
    float4 rb0 = *(const float4*)(Bp);
    float4 rb1 = *(const float4*)(Bp + (size_t)64 * Kd);

    for (int k0 = 0; k0 < Kd; k0 += 16) {
        // stage (with tf32 rounding) into smem
        uint4 u;
        u.x = f2tf(ra0.x); u.y = f2tf(ra0.y); u.z = f2tf(ra0.z); u.w = f2tf(ra0.w);
        *(uint4*)&As[sr * SMS + sc] = u;
        u.x = f2tf(ra1.x); u.y = f2tf(ra1.y); u.z = f2tf(ra1.z); u.w = f2tf(ra1.w);
        *(uint4*)&As[(sr + 64) * SMS + sc] = u;
        u.x = f2tf(rb0.x); u.y = f2tf(rb0.y); u.z = f2tf(rb0.z); u.w = f2tf(rb0.w);
        *(uint4*)&Bs[sr * SMS + sc] = u;
        u.x = f2tf(rb1.x); u.y = f2tf(rb1.y); u.z = f2tf(rb1.z); u.w = f2tf(rb1.w);
        *(uint4*)&Bs[(sr + 64) * SMS + sc] = u;
        __syncthreads();

        // prefetch next tile into registers (overlaps with MMA below)
        if (k0 + 16 < Kd) {
            ra0 = *(const float4*)(Ap + k0 + 16);
            ra1 = *(const float4*)(Ap + (size_t)64 * Kd + k0 + 16);
            rb0 = *(const float4*)(Bp + k0 + 16);
            rb1 = *(const float4*)(Bp + (size_t)64 * Kd + k0 + 16);
        }

#pragma unroll
        for (int kk = 0; kk < 16; kk += 8) {
            uint32_t af[4][4], bf[4][2];
#pragma unroll
            for (int mt = 0; mt < 4; mt++) {
                int r0 = wm + mt * 16 + g;
                af[mt][0] = As[r0 * SMS + kk + c];
                af[mt][1] = As[(r0 + 8) * SMS + kk + c];
                af[mt][2] = As[r0 * SMS + kk + c + 4];
                af[mt][3] = As[(r0 + 8) * SMS + kk + c + 4];
            }
#pragma unroll
            for (int nt = 0; nt < 4; nt++) {
                int n0 = wn + nt * 8 + g;
                bf[nt][0] = Bs[n0 * SMS + kk + c];
                bf[nt][1] = Bs[n0 * SMS + kk + c + 4];
            }
#pragma unroll
            for (int mt = 0; mt < 4; mt++)
#pragma unroll
                for (int nt = 0; nt < 4; nt++)
                    mma_tf32(acc[mt][nt], af[mt], bf[nt]);
        }
        __syncthreads();
    }

    // epilogue
#pragma unroll
    for (int mt = 0; mt < 4; mt++) {
#pragma unroll
        for (int nt = 0; nt < 4; nt++) {
            int row = blockIdx.y * 128 + wm + mt * 16 + g;
            int col = blockIdx.x * 128 + wn + nt * 8 + c * 2;
            float2 v0 = {acc[mt][nt][0], acc[mt][nt][1]};
            float2 v1 = {acc[mt][nt][2], acc[mt][nt][3]};
            *(float2*)(C + (size_t)row * N + col)       = v0;
            *(float2*)(C + (size_t)(row + 8) * N + col) = v1;
        }
    }
}

// ---------------------------------------------------------------------------
// Fused per-head RMSNorm + RoPE, in-place on X[S, nheads*128].
// One warp per (s, head) row. rotate_half via shfl_xor(16).
// ---------------------------------------------------------------------------
__global__ void rms_rope_kernel(float* __restrict__ X, const float* __restrict__ w,
                                const float* __restrict__ cosp, const float* __restrict__ sinp,
                                int nheads, int nrows) {
    int warp = (blockIdx.x * blockDim.x + threadIdx.x) >> 5;
    int lane = threadIdx.x & 31;
    if (warp >= nrows) return;
    int s = warp / nheads;

    float* p = X + (size_t)warp * HD;
    float4 x = *(float4*)(p + lane * 4);

    float ss = x.x * x.x + x.y * x.y + x.z * x.z + x.w * x.w;
#pragma unroll
    for (int o = 16; o; o >>= 1) ss += __shfl_xor_sync(0xffffffffu, ss, o);
    float r = rsqrtf(ss * (1.0f / HD) + 1e-6f);

    float4 wv = *(const float4*)(w + lane * 4);
    x.x *= r * wv.x; x.y *= r * wv.y; x.z *= r * wv.z; x.w *= r * wv.w;

    float4 rot;
    rot.x = __shfl_xor_sync(0xffffffffu, x.x, 16);
    rot.y = __shfl_xor_sync(0xffffffffu, x.y, 16);
    rot.z = __shfl_xor_sync(0xffffffffu, x.z, 16);
    rot.w = __shfl_xor_sync(0xffffffffu, x.w, 16);
    float sgn = (lane < 16) ? -1.f : 1.f;

    float4 cv = *(const float4*)(cosp + (size_t)s * HD + lane * 4);
    float4 sv = *(const float4*)(sinp + (size_t)s * HD + lane * 4);

    float4 o;
    o.x = x.x * cv.x + sgn * rot.x * sv.x;
    o.y = x.y * cv.y + sgn * rot.y * sv.y;
    o.z = x.z * cv.z + sgn * rot.z * sv.z;
    o.w = x.w * cv.w + sgn * rot.w * sv.w;
    *(float4*)(p + lane * 4) = o;
}

// ---------------------------------------------------------------------------
// Causal GQA flash attention (online softmax).
// Block: 512 threads = 16 warps, 16 query rows of one head.
// K/V tiles of 64 rows staged in dynamic smem (64KB).
// ---------------------------------------------------------------------------
__global__ void __launch_bounds__(512) flash_kernel(const float* __restrict__ Q,
                                                    const float* __restrict__ K,
                                                    const float* __restrict__ V,
                                                    float* __restrict__ O) {
    extern __shared__ float sm[];
    float* Ks = sm;              // [64][128]
    float* Vs = sm + 64 * 128;   // [64][128]

    const int tid  = threadIdx.x;
    const int w    = tid >> 5;
    const int lane = tid & 31;
    const int h    = blockIdx.y;
    const int kvh  = h >> 2;
    const int s    = blockIdx.x * 16 + w;
    const float scale = 0.08838834764831845f;  // 1/sqrt(128)

    float4 qv = *(const float4*)(Q + (size_t)s * QDIM + h * HD + lane * 4);
    float4 acc = {0.f, 0.f, 0.f, 0.f};
    float m = -1e30f, l = 0.f;

    const int smax = blockIdx.x * 16 + 15;
    for (int kb = 0; kb <= smax; kb += 64) {
#pragma unroll
        for (int i = 0; i < 4; i++) {
            int f = tid + i * 512;
            int r = f >> 5, c4 = (f & 31) * 4;
            *(float4*)(Ks + r * 128 + c4) =
                *(const float4*)(K + (size_t)(kb + r) * KVDIM + kvh * HD + c4);
            *(float4*)(Vs + r * 128 + c4) =
                *(const float4*)(V + (size_t)(kb + r) * KVDIM + kvh * HD + c4);
        }
        __syncthreads();

        int jmax = s - kb + 1;
        if (jmax > 64) jmax = 64;
        for (int j = 0; j < jmax; j++) {
            float4 kv = *(const float4*)(Ks + j * 128 + lane * 4);
            float d = qv.x * kv.x + qv.y * kv.y + qv.z * kv.z + qv.w * kv.w;
#pragma unroll
            for (int o = 16; o; o >>= 1) d += __shfl_xor_sync(0xffffffffu, d, o);
            float sc = d * scale;
            float mn = fmaxf(m, sc);
            float corr = __expf(m - mn);
            float p = __expf(sc - mn);
            l = l * corr + p;
            float4 vv = *(const float4*)(Vs + j * 128 + lane * 4);
            acc.x = acc.x * corr + p * vv.x;
            acc.y = acc.y * corr + p * vv.y;
            acc.z = acc.z * corr + p * vv.z;
            acc.w = acc.w * corr + p * vv.w;
            m = mn;
        }
        __syncthreads();
    }

    float inv = 1.f / l;
    float4 o = {acc.x * inv, acc.y * inv, acc.z * inv, acc.w * inv};
    *(float4*)(O + (size_t)s * QDIM + h * HD + lane * 4) = o;
}

// ---------------------------------------------------------------------------
extern "C" void kernel_launch(void* const* d_in, const int* in_sizes, int n_in,
                              void* d_out, int out_size) {
    const float* X    = (const float*)d_in[0];
    const float* cosp = (const float*)d_in[1];
    const float* sinp = (const float*)d_in[2];
    const float* Wq   = (const float*)d_in[3];
    const float* Wk   = (const float*)d_in[4];
    const float* Wv   = (const float*)d_in[5];
    const float* Wo   = (const float*)d_in[6];
    const float* qw   = (const float*)d_in[7];
    const float* kw   = (const float*)d_in[8];
    float* out = (float*)d_out;

    float *Q, *K, *V, *AO;
    cudaGetSymbolAddress((void**)&Q,  g_Q);
    cudaGetSymbolAddress((void**)&K,  g_K);
    cudaGetSymbolAddress((void**)&V,  g_V);
    cudaGetSymbolAddress((void**)&AO, g_AO);

    // Projections: C = X @ W^T  (TF32 tensor cores)
    tf32_gemm_nt<<<dim3(QDIM / 128,  S_LEN / 128), 256>>>(X, Wq, Q, S_LEN, QDIM,  HID);
    tf32_gemm_nt<<<dim3(KVDIM / 128, S_LEN / 128), 256>>>(X, Wk, K, S_LEN, KVDIM, HID);
    tf32_gemm_nt<<<dim3(KVDIM / 128, S_LEN / 128), 256>>>(X, Wv, V, S_LEN, KVDIM, HID);

    // RMSNorm + RoPE (in place)
    rms_rope_kernel<<<(S_LEN * NH)  / 8, 256>>>(Q, qw, cosp, sinp, NH,  S_LEN * NH);
    rms_rope_kernel<<<(S_LEN * NKV) / 8, 256>>>(K, kw, cosp, sinp, NKV, S_LEN * NKV);

    // Flash attention
    int smem = 2 * 64 * 128 * sizeof(float);  // 64KB
    cudaFuncSetAttribute(flash_kernel, cudaFuncAttributeMaxDynamicSharedMemorySize, smem);
    flash_kernel<<<dim3(S_LEN / 16, NH), 512, smem>>>(Q, K, V, AO);

    // Output projection: out = AO @ Wo^T  (TF32 tensor cores)
    tf32_gemm_nt<<<dim3(HID / 128, S_LEN / 128), 256>>>(AO, Wo, out, S_LEN, HID, QDIM);
}